// round 16
// baseline (speedup 1.0000x reference)
#include <cuda_runtime.h>
#include <cuda_bf16.h>
#include <math.h>
#include <stdint.h>

// expm(S) for 4096 skew-symmetric 64x64 matrices.
// Scaling & squaring (s=4), degree-9 Paterson-Stockmeyer, 9 matmuls of 64^3.
// mma.sync.m16n8k16 bf16 split hi/lo, fp32 accumulate. R15 config (4 CTAs/SM,
// keep-cache, B-prefetch, split epilogue, ping-pong squarings, graded
// precision) PLUS a one-time per-CTA phase-stagger delay so co-resident CTAs
// de-phase: each CTA's epilogue/barrier bubble is covered by a neighbor
// CTA's HMMA burst instead of idling the tensor pipe in lockstep.

#define LDO 136     // operand pitch in bf16 elems (272 B -> conflict-free LDSM)
#define SBP 66      // fp32 skew-matrix pitch

#define SM_X   0        // X buffer: 64 rows x [hi 64 | lo 64] bf16 -> 17408 B
#define SM_Y   17408    // Y buffer: B2 during chain, ping-pong in squarings
#define SM_SB  34816    // fp32 skew matrix, pitch 66 -> 16896 B
#define SMEM_BYTES 51712

static __device__ __forceinline__ uint32_t smem_u32(const void* p) {
    uint32_t a;
    asm("{ .reg .u64 t; cvta.to.shared.u64 t, %1; cvt.u32.u64 %0, t; }" : "=r"(a) : "l"(p));
    return a;
}
static __device__ __forceinline__ void ldsm4(uint32_t* r, uint32_t a) {
    asm volatile("ldmatrix.sync.aligned.m8n8.x4.shared.b16 {%0,%1,%2,%3}, [%4];"
        : "=r"(r[0]), "=r"(r[1]), "=r"(r[2]), "=r"(r[3]) : "r"(a));
}
static __device__ __forceinline__ void ldsm4t(uint32_t* r, uint32_t a) {
    asm volatile("ldmatrix.sync.aligned.m8n8.x4.trans.shared.b16 {%0,%1,%2,%3}, [%4];"
        : "=r"(r[0]), "=r"(r[1]), "=r"(r[2]), "=r"(r[3]) : "r"(a));
}
static __device__ __forceinline__ void mma16816(float* c, const uint32_t* a, const uint32_t* b) {
    asm volatile("mma.sync.aligned.m16n8k16.row.col.f32.bf16.bf16.f32 "
        "{%0,%1,%2,%3}, {%4,%5,%6,%7}, {%8,%9}, {%0,%1,%2,%3};"
        : "+f"(c[0]), "+f"(c[1]), "+f"(c[2]), "+f"(c[3])
        : "r"(a[0]), "r"(a[1]), "r"(a[2]), "r"(a[3]), "r"(b[0]), "r"(b[1]));
}
// hw = bf16x2(x1,x0), lw = bf16x2 of residuals
static __device__ __forceinline__ void splitw(float x0, float x1, uint32_t& hw, uint32_t& lw) {
    asm("cvt.rn.bf16x2.f32 %0, %1, %2;" : "=r"(hw) : "f"(x1), "f"(x0));
    float h0 = __uint_as_float(hw << 16);
    float h1 = __uint_as_float(hw & 0xffff0000u);
    float r0 = x0 - h0, r1 = x1 - h1;
    asm("cvt.rn.bf16x2.f32 %0, %1, %2;" : "=r"(lw) : "f"(r1), "f"(r0));
}

// Split-product MMA block for one k-tile.
// NPROD==3: Ah*Bh + Ah*Bl + Al*Bh; ==2: Ah*Bh + Ah*Bl; ==1: Ah*Bh.
template <int NPROD>
static __device__ __forceinline__ void prod_all(
    float c[2][4][4],
    const uint32_t* ah0, const uint32_t* ah1,
    const uint32_t* al0, const uint32_t* al1,
    const uint32_t bh[2][4], const uint32_t bl[2][4])
{
#pragma unroll
    for (int t = 0; t < 2; t++) {
        mma16816(c[0][2 * t],     ah0, bh[t]);
        mma16816(c[0][2 * t + 1], ah0, bh[t] + 2);
        mma16816(c[1][2 * t],     ah1, bh[t]);
        mma16816(c[1][2 * t + 1], ah1, bh[t] + 2);
        if (NPROD >= 2) {
            mma16816(c[0][2 * t],     ah0, bl[t]);
            mma16816(c[0][2 * t + 1], ah0, bl[t] + 2);
            mma16816(c[1][2 * t],     ah1, bl[t]);
            mma16816(c[1][2 * t + 1], ah1, bl[t] + 2);
        }
        if (NPROD >= 3) {
            mma16816(c[0][2 * t],     al0, bh[t]);
            mma16816(c[0][2 * t + 1], al0, bh[t] + 2);
            mma16816(c[1][2 * t],     al1, bh[t]);
            mma16816(c[1][2 * t + 1], al1, bh[t] + 2);
        }
    }
}

template <int NPROD>
static __device__ __forceinline__ void ldB(uint32_t bh[2][4], uint32_t bl[2][4], uint32_t bk) {
    ldsm4t(bh[0], bk);
    ldsm4t(bh[1], bk + 32);
    if (NPROD >= 2) {
        ldsm4t(bl[0], bk + 128);
        ldsm4t(bl[1], bk + 32 + 128);
    }
}
template <int NPROD>
static __device__ __forceinline__ void ldA(uint32_t ah[2][4], uint32_t al[2][4],
                                           uint32_t aA, uint32_t rstep, uint32_t ko) {
    ldsm4(ah[0], aA + ko);
    ldsm4(ah[1], aA + rstep + ko);
    if (NPROD >= 3) {
        ldsm4(al[0], aA + 128 + ko);
        ldsm4(al[1], aA + rstep + 128 + ko);
    }
}

// C(64x64) = A * B with B-fragment prefetch one k-tile ahead.
// UK: A-frags for the warp's own first two k-tiles come from the keep cache.
template <bool UK, int NPROD>
static __device__ __forceinline__ void mm_compute(
    float c[2][4][4], uint32_t aBase, uint32_t bBase,
    const uint32_t kH[2][2][4], const uint32_t kL[2][2][4],
    int wid, int lid)
{
#pragma unroll
    for (int m = 0; m < 2; m++)
#pragma unroll
        for (int j = 0; j < 4; j++)
#pragma unroll
            for (int q = 0; q < 4; q++) c[m][j][q] = 0.f;

    const int r0 = (wid >> 1) * 32, c0 = (wid & 1) * 32;
    const uint32_t aA = aBase + (uint32_t)((r0 + (lid & 15)) * LDO + (lid >> 4) * 8) * 2;
    const uint32_t bA = bBase
        + (uint32_t)(((lid & 7) + ((lid & 8) ? 8 : 0)) * LDO + c0 + ((lid & 16) ? 8 : 0)) * 2;
    const uint32_t rstep = 16 * LDO * 2;
    const int ownkt = c0 >> 4;   // 0 or 2

    const int kts[4] = { ownkt, ownkt + 1, 2 - ownkt, 3 - ownkt };

    uint32_t bh[2][2][4], bl[2][2][4];
    ldB<NPROD>(bh[0], bl[0], bA + (uint32_t)kts[0] * rstep);

#pragma unroll
    for (int i = 0; i < 4; i++) {
        const int cur = i & 1;
        uint32_t ah[2][4], al[2][4];
        const bool useKeep = UK && (i < 2);
        if (!useKeep)
            ldA<NPROD>(ah, al, aA, rstep, (uint32_t)kts[i] * 32);
        if (i < 3)
            ldB<NPROD>(bh[cur ^ 1], bl[cur ^ 1], bA + (uint32_t)kts[i + 1] * rstep);
        if (useKeep)
            prod_all<NPROD>(c, kH[0][i], kH[1][i], kL[0][i], kL[1][i], bh[cur], bl[cur]);
        else
            prod_all<NPROD>(c, ah[0], ah[1], al[0], al[1], bh[cur], bl[cur]);
    }
}

// Pre-barrier: apply LIN (optional), then splitw IN PLACE: c pairs -> packed bits.
template <bool LIN>
static __device__ __forceinline__ void epi_compute(
    float c[2][4][4], const float* sB, int wid, int lid, float aI, float bB)
{
    const int g = lid >> 2, tg = lid & 3;
    const int r0 = (wid >> 1) * 32, c0 = (wid & 1) * 32;
#pragma unroll
    for (int m = 0; m < 2; m++) {
#pragma unroll
        for (int j = 0; j < 4; j++) {
            const int col = c0 + 8 * j + 2 * tg;
#pragma unroll
            for (int h = 0; h < 2; h++) {
                const int row = r0 + 16 * m + 8 * h + g;
                float x0 = c[m][j][2 * h], x1 = c[m][j][2 * h + 1];
                if (LIN) {
                    float2 bv = *reinterpret_cast<const float2*>(sB + row * SBP + col);
                    x0 += bB * bv.x;
                    x1 += bB * bv.y;
                    if (col == row) x0 += aI;
                    if (col + 1 == row) x1 += aI;
                }
                uint32_t hw, lw;
                splitw(x0, x1, hw, lw);
                c[m][j][2 * h]     = __uint_as_float(hw);
                c[m][j][2 * h + 1] = __uint_as_float(lw);
            }
        }
    }
}

// STS of packed bits; WK keeps own quadrant for the next GEMM.
template <bool WK>
static __device__ __forceinline__ void epi_store(
    const float c[2][4][4], __nv_bfloat16* dst,
    uint32_t kH[2][2][4], uint32_t kL[2][2][4], int wid, int lid)
{
    const int g = lid >> 2, tg = lid & 3;
    const int r0 = (wid >> 1) * 32, c0 = (wid & 1) * 32;
#pragma unroll
    for (int m = 0; m < 2; m++) {
#pragma unroll
        for (int j = 0; j < 4; j++) {
            const int col = c0 + 8 * j + 2 * tg;
#pragma unroll
            for (int h = 0; h < 2; h++) {
                const int row = r0 + 16 * m + 8 * h + g;
                const uint32_t hw = __float_as_uint(c[m][j][2 * h]);
                const uint32_t lw = __float_as_uint(c[m][j][2 * h + 1]);
                *reinterpret_cast<uint32_t*>(dst + row * LDO + col) = hw;
                *reinterpret_cast<uint32_t*>(dst + row * LDO + 64 + col) = lw;
                if (WK) {
                    kH[m][j >> 1][(j & 1) * 2 + h] = hw;
                    kL[m][j >> 1][(j & 1) * 2 + h] = lw;
                }
            }
        }
    }
}

// Final: fp32 result straight to global.
static __device__ __forceinline__ void epi_gm(
    const float c[2][4][4], float* gout, int wid, int lid)
{
    const int g = lid >> 2, tg = lid & 3;
    const int r0 = (wid >> 1) * 32, c0 = (wid & 1) * 32;
#pragma unroll
    for (int m = 0; m < 2; m++)
#pragma unroll
        for (int j = 0; j < 4; j++) {
            const int col = c0 + 8 * j + 2 * tg;
#pragma unroll
            for (int h = 0; h < 2; h++) {
                const int row = r0 + 16 * m + 8 * h + g;
                *reinterpret_cast<float2*>(gout + row * 64 + col) =
                    make_float2(c[m][j][2 * h], c[m][j][2 * h + 1]);
            }
        }
}

__global__ void __launch_bounds__(128, 4)
SkewSymMatrixExp_kernel(const float* __restrict__ Svec, float* __restrict__ out)
{
    extern __shared__ char smem[];
    const uint32_t sb = smem_u32(smem);
    __nv_bfloat16* Xbuf = reinterpret_cast<__nv_bfloat16*>(smem + SM_X);
    __nv_bfloat16* Ybuf = reinterpret_cast<__nv_bfloat16*>(smem + SM_Y);
    float* sB = reinterpret_cast<float*>(smem + SM_SB);

    const int tid = threadIdx.x, wid = tid >> 5, lid = tid & 31;
    const float* v = Svec + (size_t)blockIdx.x * 2016;

    // ---- phase-stagger: de-phase co-resident CTAs by quarter-period steps so
    // their epilogue bubbles are covered by neighbors' HMMA bursts.
    {
        const unsigned long long target = (unsigned long long)((blockIdx.x & 3) * 340);
        if (target) {
            const unsigned long long t0 = clock64();
            while (clock64() - t0 < target) { }
        }
    }

    // ---- scatter S_vec into fp32 skew matrix B = S/16
    if (tid < 64) sB[tid * SBP + tid] = 0.f;
    const float scl = 0.0625f;
    for (int n = tid; n < 2016; n += 128) {
        int i = (int)((127.0f - sqrtf(16129.0f - 8.0f * (float)n)) * 0.5f);
        if (i < 0) i = 0;
        if (i > 62) i = 62;
        while ((((i + 1) * (126 - i)) >> 1) <= n) ++i;
        while (((i * (127 - i)) >> 1) > n) --i;
        int j = i + 1 + (n - ((i * (127 - i)) >> 1));
        float val = v[n] * scl;
        sB[i * SBP + j] = -val;
        sB[j * SBP + i] = val;
    }
    __syncthreads();

    // ---- initial X = split(B), row-major
    {
        const int r = tid >> 1;
        const int k0 = (tid & 1) * 32;
#pragma unroll 8
        for (int kk = k0; kk < k0 + 32; kk += 2) {
            float x0 = sB[r * SBP + kk], x1 = sB[r * SBP + kk + 1];
            uint32_t hw, lw;
            splitw(x0, x1, hw, lw);
            *reinterpret_cast<uint32_t*>(Xbuf + r * LDO + kk) = hw;
            *reinterpret_cast<uint32_t*>(Xbuf + r * LDO + 64 + kk) = lw;
        }
    }
    __syncthreads();

    // Taylor coeffs a_i = 1/(2i)!, b_i = 1/(2i+1)!
    const float A4 = 2.4801587e-5f, B4 = 2.7557319e-6f;
    const float A3 = 1.3888889e-3f, B3 = 1.9841270e-4f;
    const float A2 = 4.1666668e-2f, B2c = 8.3333333e-3f;
    const float A1 = 0.5f, B1 = 1.6666667e-1f;

    float c[2][4][4];
    uint32_t kH[2][2][4], kL[2][2][4];

    // ---- step 0: B2 = B*B -> Ybuf (pre-barrier; Y unread this step).
    mm_compute<false, 3>(c, sb + SM_X, sb + SM_X, kH, kL, wid, lid);
    epi_compute<false>(c, sB, wid, lid, 0.f, 0.f);
    epi_store<true>(c, Ybuf, kH, kL, wid, lid);
    // r4 = A4*I + B4*B: compute packed words into c's (dead) registers pre-barrier
    {
        const int r = tid >> 1;
        const int k0 = (tid & 1) * 32;
        float* cf = &c[0][0][0];
#pragma unroll
        for (int ii = 0; ii < 16; ii++) {
            const int kk = k0 + 2 * ii;
            float x0 = B4 * sB[r * SBP + kk] + (kk == r ? A4 : 0.f);
            float x1 = B4 * sB[r * SBP + kk + 1] + (kk + 1 == r ? A4 : 0.f);
            uint32_t hw, lw;
            splitw(x0, x1, hw, lw);
            cf[2 * ii] = __uint_as_float(hw);
            cf[2 * ii + 1] = __uint_as_float(lw);
        }
    }
    __syncthreads();   // all warps done reading X
    {
        const int r = tid >> 1;
        const int k0 = (tid & 1) * 32;
        const float* cf = &c[0][0][0];
#pragma unroll
        for (int ii = 0; ii < 16; ii++) {
            const int kk = k0 + 2 * ii;
            *reinterpret_cast<uint32_t*>(Xbuf + r * LDO + kk) = __float_as_uint(cf[2 * ii]);
            *reinterpret_cast<uint32_t*>(Xbuf + r * LDO + 64 + kk) = __float_as_uint(cf[2 * ii + 1]);
        }
    }
    __syncthreads();

    // ---- chain step 1: r3 = A3 I + B3 B + B2*r4   (‖r4‖~2.5e-5 -> 1 product)
    mm_compute<true, 1>(c, sb + SM_Y, sb + SM_X, kH, kL, wid, lid);
    epi_compute<true>(c, sB, wid, lid, A3, B3);
    __syncthreads();
    epi_store<false>(c, Xbuf, kH, kL, wid, lid);
    __syncthreads();

    // ---- chain step 2: r2 = A2 I + B2c B + B2*r3  (‖r3‖~1.4e-3 -> 2 products)
    mm_compute<true, 2>(c, sb + SM_Y, sb + SM_X, kH, kL, wid, lid);
    epi_compute<true>(c, sB, wid, lid, A2, B2c);
    __syncthreads();
    epi_store<false>(c, Xbuf, kH, kL, wid, lid);
    __syncthreads();

    // ---- chain step 3: r1 = A1 I + B1 B + B2*r2  (full precision)
    mm_compute<true, 3>(c, sb + SM_Y, sb + SM_X, kH, kL, wid, lid);
    epi_compute<true>(c, sB, wid, lid, A1, B1);
    __syncthreads();
    epi_store<false>(c, Xbuf, kH, kL, wid, lid);
    __syncthreads();

    // ---- step 4: P = I + B + B2*r1 -> Xbuf (keep <- P quadrant)
    mm_compute<true, 3>(c, sb + SM_Y, sb + SM_X, kH, kL, wid, lid);
    epi_compute<true>(c, sB, wid, lid, 1.f, 1.f);
    __syncthreads();
    epi_store<true>(c, Xbuf, kH, kL, wid, lid);
    __syncthreads();

    // ---- squarings: ping-pong X <-> Y, full epilogue BEFORE the single barrier
    mm_compute<true, 3>(c, sb + SM_X, sb + SM_X, kH, kL, wid, lid);   // sq1: X -> Y
    epi_compute<false>(c, sB, wid, lid, 0.f, 0.f);
    epi_store<true>(c, Ybuf, kH, kL, wid, lid);
    __syncthreads();
    mm_compute<true, 3>(c, sb + SM_Y, sb + SM_Y, kH, kL, wid, lid);   // sq2: Y -> X
    epi_compute<false>(c, sB, wid, lid, 0.f, 0.f);
    epi_store<true>(c, Xbuf, kH, kL, wid, lid);
    __syncthreads();
    mm_compute<true, 3>(c, sb + SM_X, sb + SM_X, kH, kL, wid, lid);   // sq3: X -> Y
    epi_compute<false>(c, sB, wid, lid, 0.f, 0.f);
    epi_store<true>(c, Ybuf, kH, kL, wid, lid);
    __syncthreads();
    mm_compute<true, 3>(c, sb + SM_Y, sb + SM_Y, kH, kL, wid, lid);   // sq4: Y -> gmem
    epi_gm(c, out + (size_t)blockIdx.x * 4096, wid, lid);
}

extern "C" void kernel_launch(void* const* d_in, const int* in_sizes, int n_in,
                              void* d_out, int out_size)
{
    const float* svec = (const float*)d_in[0];
    float* out = (float*)d_out;
    const int batch = in_sizes[0] / 2016;

    cudaFuncSetAttribute(SkewSymMatrixExp_kernel,
                         cudaFuncAttributeMaxDynamicSharedMemorySize, SMEM_BYTES);
    SkewSymMatrixExp_kernel<<<batch, 128, SMEM_BYTES>>>(svec, out);
}

// round 17
// speedup vs baseline: 1.0644x; 1.0644x over previous
#include <cuda_runtime.h>
#include <cuda_bf16.h>
#include <math.h>
#include <stdint.h>

// expm(S) for 4096 skew-symmetric 64x64 matrices.
// Scaling & squaring (s=4) with a DEGREE-7 CHEBYSHEV-ECONOMIZED polynomial:
// e^B = C(B2) + B*S(B2), C/S economized on u = B2 in [-1.5625, 0] (u^4 terms
// folded into cubics via shifted-Chebyshev T4). 8 matmuls of 64^3 (was 9).
// mma.sync.m16n8k16 bf16 split hi/lo, graded products, fp32 accumulate.
// 4 CTAs/SM, keep-cache, B-prefetch, split epilogue, ping-pong squarings.

#define LDO 136     // operand pitch in bf16 elems (272 B -> conflict-free LDSM)
#define SBP 66      // fp32 skew-matrix pitch

#define SM_X   0        // X buffer: 64 rows x [hi 64 | lo 64] bf16 -> 17408 B
#define SM_Y   17408    // Y buffer: B2 during chain, ping-pong in squarings
#define SM_SB  34816    // fp32 skew matrix, pitch 66 -> 16896 B
#define SMEM_BYTES 51712

static __device__ __forceinline__ uint32_t smem_u32(const void* p) {
    uint32_t a;
    asm("{ .reg .u64 t; cvta.to.shared.u64 t, %1; cvt.u32.u64 %0, t; }" : "=r"(a) : "l"(p));
    return a;
}
static __device__ __forceinline__ void ldsm4(uint32_t* r, uint32_t a) {
    asm volatile("ldmatrix.sync.aligned.m8n8.x4.shared.b16 {%0,%1,%2,%3}, [%4];"
        : "=r"(r[0]), "=r"(r[1]), "=r"(r[2]), "=r"(r[3]) : "r"(a));
}
static __device__ __forceinline__ void ldsm4t(uint32_t* r, uint32_t a) {
    asm volatile("ldmatrix.sync.aligned.m8n8.x4.trans.shared.b16 {%0,%1,%2,%3}, [%4];"
        : "=r"(r[0]), "=r"(r[1]), "=r"(r[2]), "=r"(r[3]) : "r"(a));
}
static __device__ __forceinline__ void mma16816(float* c, const uint32_t* a, const uint32_t* b) {
    asm volatile("mma.sync.aligned.m16n8k16.row.col.f32.bf16.bf16.f32 "
        "{%0,%1,%2,%3}, {%4,%5,%6,%7}, {%8,%9}, {%0,%1,%2,%3};"
        : "+f"(c[0]), "+f"(c[1]), "+f"(c[2]), "+f"(c[3])
        : "r"(a[0]), "r"(a[1]), "r"(a[2]), "r"(a[3]), "r"(b[0]), "r"(b[1]));
}
// hw = bf16x2(x1,x0), lw = bf16x2 of residuals
static __device__ __forceinline__ void splitw(float x0, float x1, uint32_t& hw, uint32_t& lw) {
    asm("cvt.rn.bf16x2.f32 %0, %1, %2;" : "=r"(hw) : "f"(x1), "f"(x0));
    float h0 = __uint_as_float(hw << 16);
    float h1 = __uint_as_float(hw & 0xffff0000u);
    float r0 = x0 - h0, r1 = x1 - h1;
    asm("cvt.rn.bf16x2.f32 %0, %1, %2;" : "=r"(lw) : "f"(r1), "f"(r0));
}

// Split-product MMA block for one k-tile.
// NPROD==3: Ah*Bh + Ah*Bl + Al*Bh; ==2: Ah*Bh + Ah*Bl; ==1: Ah*Bh.
template <int NPROD>
static __device__ __forceinline__ void prod_all(
    float c[2][4][4],
    const uint32_t* ah0, const uint32_t* ah1,
    const uint32_t* al0, const uint32_t* al1,
    const uint32_t bh[2][4], const uint32_t bl[2][4])
{
#pragma unroll
    for (int t = 0; t < 2; t++) {
        mma16816(c[0][2 * t],     ah0, bh[t]);
        mma16816(c[0][2 * t + 1], ah0, bh[t] + 2);
        mma16816(c[1][2 * t],     ah1, bh[t]);
        mma16816(c[1][2 * t + 1], ah1, bh[t] + 2);
        if (NPROD >= 2) {
            mma16816(c[0][2 * t],     ah0, bl[t]);
            mma16816(c[0][2 * t + 1], ah0, bl[t] + 2);
            mma16816(c[1][2 * t],     ah1, bl[t]);
            mma16816(c[1][2 * t + 1], ah1, bl[t] + 2);
        }
        if (NPROD >= 3) {
            mma16816(c[0][2 * t],     al0, bh[t]);
            mma16816(c[0][2 * t + 1], al0, bh[t] + 2);
            mma16816(c[1][2 * t],     al1, bh[t]);
            mma16816(c[1][2 * t + 1], al1, bh[t] + 2);
        }
    }
}

template <int NPROD>
static __device__ __forceinline__ void ldB(uint32_t bh[2][4], uint32_t bl[2][4], uint32_t bk) {
    ldsm4t(bh[0], bk);
    ldsm4t(bh[1], bk + 32);
    if (NPROD >= 2) {
        ldsm4t(bl[0], bk + 128);
        ldsm4t(bl[1], bk + 32 + 128);
    }
}
template <int NPROD>
static __device__ __forceinline__ void ldA(uint32_t ah[2][4], uint32_t al[2][4],
                                           uint32_t aA, uint32_t rstep, uint32_t ko) {
    ldsm4(ah[0], aA + ko);
    ldsm4(ah[1], aA + rstep + ko);
    if (NPROD >= 3) {
        ldsm4(al[0], aA + 128 + ko);
        ldsm4(al[1], aA + rstep + 128 + ko);
    }
}

// C(64x64) = A * B with B-fragment prefetch one k-tile ahead.
// UK: A-frags for the warp's own first two k-tiles come from the keep cache.
template <bool UK, int NPROD>
static __device__ __forceinline__ void mm_compute(
    float c[2][4][4], uint32_t aBase, uint32_t bBase,
    const uint32_t kH[2][2][4], const uint32_t kL[2][2][4],
    int wid, int lid)
{
#pragma unroll
    for (int m = 0; m < 2; m++)
#pragma unroll
        for (int j = 0; j < 4; j++)
#pragma unroll
            for (int q = 0; q < 4; q++) c[m][j][q] = 0.f;

    const int r0 = (wid >> 1) * 32, c0 = (wid & 1) * 32;
    const uint32_t aA = aBase + (uint32_t)((r0 + (lid & 15)) * LDO + (lid >> 4) * 8) * 2;
    const uint32_t bA = bBase
        + (uint32_t)(((lid & 7) + ((lid & 8) ? 8 : 0)) * LDO + c0 + ((lid & 16) ? 8 : 0)) * 2;
    const uint32_t rstep = 16 * LDO * 2;
    const int ownkt = c0 >> 4;   // 0 or 2

    const int kts[4] = { ownkt, ownkt + 1, 2 - ownkt, 3 - ownkt };

    uint32_t bh[2][2][4], bl[2][2][4];
    ldB<NPROD>(bh[0], bl[0], bA + (uint32_t)kts[0] * rstep);

#pragma unroll
    for (int i = 0; i < 4; i++) {
        const int cur = i & 1;
        uint32_t ah[2][4], al[2][4];
        const bool useKeep = UK && (i < 2);
        if (!useKeep)
            ldA<NPROD>(ah, al, aA, rstep, (uint32_t)kts[i] * 32);
        if (i < 3)
            ldB<NPROD>(bh[cur ^ 1], bl[cur ^ 1], bA + (uint32_t)kts[i + 1] * rstep);
        if (useKeep)
            prod_all<NPROD>(c, kH[0][i], kH[1][i], kL[0][i], kL[1][i], bh[cur], bl[cur]);
        else
            prod_all<NPROD>(c, ah[0], ah[1], al[0], al[1], bh[cur], bl[cur]);
    }
}

// Pre-barrier: apply LIN (optional), then splitw IN PLACE: c pairs -> packed bits.
template <bool LIN>
static __device__ __forceinline__ void epi_compute(
    float c[2][4][4], const float* sB, int wid, int lid, float aI, float bB)
{
    const int g = lid >> 2, tg = lid & 3;
    const int r0 = (wid >> 1) * 32, c0 = (wid & 1) * 32;
#pragma unroll
    for (int m = 0; m < 2; m++) {
#pragma unroll
        for (int j = 0; j < 4; j++) {
            const int col = c0 + 8 * j + 2 * tg;
#pragma unroll
            for (int h = 0; h < 2; h++) {
                const int row = r0 + 16 * m + 8 * h + g;
                float x0 = c[m][j][2 * h], x1 = c[m][j][2 * h + 1];
                if (LIN) {
                    float2 bv = *reinterpret_cast<const float2*>(sB + row * SBP + col);
                    x0 += bB * bv.x;
                    x1 += bB * bv.y;
                    if (col == row) x0 += aI;
                    if (col + 1 == row) x1 += aI;
                }
                uint32_t hw, lw;
                splitw(x0, x1, hw, lw);
                c[m][j][2 * h]     = __uint_as_float(hw);
                c[m][j][2 * h + 1] = __uint_as_float(lw);
            }
        }
    }
}

// STS of packed bits; WK keeps own quadrant for the next GEMM.
template <bool WK>
static __device__ __forceinline__ void epi_store(
    const float c[2][4][4], __nv_bfloat16* dst,
    uint32_t kH[2][2][4], uint32_t kL[2][2][4], int wid, int lid)
{
    const int g = lid >> 2, tg = lid & 3;
    const int r0 = (wid >> 1) * 32, c0 = (wid & 1) * 32;
#pragma unroll
    for (int m = 0; m < 2; m++) {
#pragma unroll
        for (int j = 0; j < 4; j++) {
            const int col = c0 + 8 * j + 2 * tg;
#pragma unroll
            for (int h = 0; h < 2; h++) {
                const int row = r0 + 16 * m + 8 * h + g;
                const uint32_t hw = __float_as_uint(c[m][j][2 * h]);
                const uint32_t lw = __float_as_uint(c[m][j][2 * h + 1]);
                *reinterpret_cast<uint32_t*>(dst + row * LDO + col) = hw;
                *reinterpret_cast<uint32_t*>(dst + row * LDO + 64 + col) = lw;
                if (WK) {
                    kH[m][j >> 1][(j & 1) * 2 + h] = hw;
                    kL[m][j >> 1][(j & 1) * 2 + h] = lw;
                }
            }
        }
    }
}

// Final: fp32 result straight to global.
static __device__ __forceinline__ void epi_gm(
    const float c[2][4][4], float* gout, int wid, int lid)
{
    const int g = lid >> 2, tg = lid & 3;
    const int r0 = (wid >> 1) * 32, c0 = (wid & 1) * 32;
#pragma unroll
    for (int m = 0; m < 2; m++)
#pragma unroll
        for (int j = 0; j < 4; j++) {
            const int col = c0 + 8 * j + 2 * tg;
#pragma unroll
            for (int h = 0; h < 2; h++) {
                const int row = r0 + 16 * m + 8 * h + g;
                *reinterpret_cast<float2*>(gout + row * 64 + col) =
                    make_float2(c[m][j][2 * h], c[m][j][2 * h + 1]);
            }
        }
}

__global__ void __launch_bounds__(128, 4)
SkewSymMatrixExp_kernel(const float* __restrict__ Svec, float* __restrict__ out)
{
    extern __shared__ char smem[];
    const uint32_t sb = smem_u32(smem);
    __nv_bfloat16* Xbuf = reinterpret_cast<__nv_bfloat16*>(smem + SM_X);
    __nv_bfloat16* Ybuf = reinterpret_cast<__nv_bfloat16*>(smem + SM_Y);
    float* sB = reinterpret_cast<float*>(smem + SM_SB);

    const int tid = threadIdx.x, wid = tid >> 5, lid = tid & 31;
    const float* v = Svec + (size_t)blockIdx.x * 2016;

    // ---- scatter S_vec into fp32 skew matrix B = S/16
    if (tid < 64) sB[tid * SBP + tid] = 0.f;
    const float scl = 0.0625f;
    for (int n = tid; n < 2016; n += 128) {
        int i = (int)((127.0f - sqrtf(16129.0f - 8.0f * (float)n)) * 0.5f);
        if (i < 0) i = 0;
        if (i > 62) i = 62;
        while ((((i + 1) * (126 - i)) >> 1) <= n) ++i;
        while (((i * (127 - i)) >> 1) > n) --i;
        int j = i + 1 + (n - ((i * (127 - i)) >> 1));
        float val = v[n] * scl;
        sB[i * SBP + j] = -val;
        sB[j * SBP + i] = val;
    }
    __syncthreads();

    // ---- initial X = split(B), row-major
    {
        const int r = tid >> 1;
        const int k0 = (tid & 1) * 32;
#pragma unroll 8
        for (int kk = k0; kk < k0 + 32; kk += 2) {
            float x0 = sB[r * SBP + kk], x1 = sB[r * SBP + kk + 1];
            uint32_t hw, lw;
            splitw(x0, x1, hw, lw);
            *reinterpret_cast<uint32_t*>(Xbuf + r * LDO + kk) = hw;
            *reinterpret_cast<uint32_t*>(Xbuf + r * LDO + 64 + kk) = lw;
        }
    }
    __syncthreads();

    // Degree-7 Chebyshev-economized coefficients (theta = 1.25, h = theta^2/2):
    // e^B = C(B2) + B*S(B2);  r3 = C3 I + S3 B;  r_{i} = Ci I + Si B + B2*r_{i+1}
    const float C3 = 1.3113839e-3f, S3 = 1.8980104e-4f;
    const float C2 = 4.1590979e-2f, S2 = 8.3249227e-3f;
    const float C1 = 4.9997635e-1f, S1 = 1.6666404e-1f;
    const float C0 = 9.9999885e-1f, S0 = 9.9999987e-1f;

    float c[2][4][4];
    uint32_t kH[2][2][4], kL[2][2][4];

    // ---- step 0: B2 = B*B -> Ybuf (pre-barrier; Y unread this step).
    mm_compute<false, 3>(c, sb + SM_X, sb + SM_X, kH, kL, wid, lid);
    epi_compute<false>(c, sB, wid, lid, 0.f, 0.f);
    epi_store<true>(c, Ybuf, kH, kL, wid, lid);
    // r3 = C3*I + S3*B: compute packed words into c's (dead) registers pre-barrier
    {
        const int r = tid >> 1;
        const int k0 = (tid & 1) * 32;
        float* cf = &c[0][0][0];
#pragma unroll
        for (int ii = 0; ii < 16; ii++) {
            const int kk = k0 + 2 * ii;
            float x0 = S3 * sB[r * SBP + kk] + (kk == r ? C3 : 0.f);
            float x1 = S3 * sB[r * SBP + kk + 1] + (kk + 1 == r ? C3 : 0.f);
            uint32_t hw, lw;
            splitw(x0, x1, hw, lw);
            cf[2 * ii] = __uint_as_float(hw);
            cf[2 * ii + 1] = __uint_as_float(lw);
        }
    }
    __syncthreads();   // all warps done reading X
    {
        const int r = tid >> 1;
        const int k0 = (tid & 1) * 32;
        const float* cf = &c[0][0][0];
#pragma unroll
        for (int ii = 0; ii < 16; ii++) {
            const int kk = k0 + 2 * ii;
            *reinterpret_cast<uint32_t*>(Xbuf + r * LDO + kk) = __float_as_uint(cf[2 * ii]);
            *reinterpret_cast<uint32_t*>(Xbuf + r * LDO + 64 + kk) = __float_as_uint(cf[2 * ii + 1]);
        }
    }
    __syncthreads();

    // ---- chain step 1: r2 = C2 I + S2 B + B2*r3   (‖r3‖~1.5e-3 -> 2 products)
    mm_compute<true, 2>(c, sb + SM_Y, sb + SM_X, kH, kL, wid, lid);
    epi_compute<true>(c, sB, wid, lid, C2, S2);
    __syncthreads();
    epi_store<false>(c, Xbuf, kH, kL, wid, lid);
    __syncthreads();

    // ---- chain step 2: r1 = C1 I + S1 B + B2*r2  (full precision)
    mm_compute<true, 3>(c, sb + SM_Y, sb + SM_X, kH, kL, wid, lid);
    epi_compute<true>(c, sB, wid, lid, C1, S1);
    __syncthreads();
    epi_store<false>(c, Xbuf, kH, kL, wid, lid);
    __syncthreads();

    // ---- step 3: P = C0 I + S0 B + B2*r1 -> Xbuf (keep <- P quadrant)
    mm_compute<true, 3>(c, sb + SM_Y, sb + SM_X, kH, kL, wid, lid);
    epi_compute<true>(c, sB, wid, lid, C0, S0);
    __syncthreads();
    epi_store<true>(c, Xbuf, kH, kL, wid, lid);
    __syncthreads();

    // ---- squarings: ping-pong X <-> Y, full epilogue BEFORE the single barrier
    mm_compute<true, 3>(c, sb + SM_X, sb + SM_X, kH, kL, wid, lid);   // sq1: X -> Y
    epi_compute<false>(c, sB, wid, lid, 0.f, 0.f);
    epi_store<true>(c, Ybuf, kH, kL, wid, lid);
    __syncthreads();
    mm_compute<true, 3>(c, sb + SM_Y, sb + SM_Y, kH, kL, wid, lid);   // sq2: Y -> X
    epi_compute<false>(c, sB, wid, lid, 0.f, 0.f);
    epi_store<true>(c, Xbuf, kH, kL, wid, lid);
    __syncthreads();
    mm_compute<true, 3>(c, sb + SM_X, sb + SM_X, kH, kL, wid, lid);   // sq3: X -> Y
    epi_compute<false>(c, sB, wid, lid, 0.f, 0.f);
    epi_store<true>(c, Ybuf, kH, kL, wid, lid);
    __syncthreads();
    mm_compute<true, 3>(c, sb + SM_Y, sb + SM_Y, kH, kL, wid, lid);   // sq4: Y -> gmem
    epi_gm(c, out + (size_t)blockIdx.x * 4096, wid, lid);
}

extern "C" void kernel_launch(void* const* d_in, const int* in_sizes, int n_in,
                              void* d_out, int out_size)
{
    const float* svec = (const float*)d_in[0];
    float* out = (float*)d_out;
    const int batch = in_sizes[0] / 2016;

    cudaFuncSetAttribute(SkewSymMatrixExp_kernel,
                         cudaFuncAttributeMaxDynamicSharedMemorySize, SMEM_BYTES);
    SkewSymMatrixExp_kernel<<<batch, 128, SMEM_BYTES>>>(svec, out);
}